// round 16
// baseline (speedup 1.0000x reference)
#include <cuda_runtime.h>
#include <cstdint>

// ============================================================================
// 16-qubit statevector simulator, 64 batches, 3 layers (Rot x16 + CNOT chain).
// Round 16: R15 + L2-residency work.
//  * passB / passBmeas unchanged math, but passB runs IN-PLACE (each thread
//    reads exactly the addresses it writes) -> per-layer unique-line traffic
//    96MB -> 64MB, state stays hot in L2.
//  * Layer-0 input loads use ld.global.cs (read-once, evict-first) so the
//    32MB input doesn't evict the state buffers.
//  * Buffers: A0 in->b0, B0 b0 in-place, A1 b0->b1, B1 b1 in-place,
//    A2 b1->b0, M b0.
// ============================================================================

#define THREADS   256
#define PAD_SLOTS (2048 + 256)    // slot = t + (t>>3), 16B elements

typedef unsigned long long ull;

__device__ ulonglong2 g_bufA[64 * 32768];
__device__ ulonglong2 g_bufB[64 * 32768];

struct G7 { ull ar, ai, nai, br, bi, nbr, nbi; };   // swap-free vgate coeffs
struct GL { ull p1, p2, p3, p4, q1, q2, q3, q4; };  // in-lane (bit15) coeffs

// ---------------- packed f32x2 primitives ----------------
__device__ __forceinline__ ull f2fma(ull a, ull b, ull c) {
    ull d; asm("fma.rn.f32x2 %0, %1, %2, %3;" : "=l"(d) : "l"(a), "l"(b), "l"(c));
    return d;
}
__device__ __forceinline__ ull f2mul(ull a, ull b) {
    ull d; asm("mul.rn.f32x2 %0, %1, %2;" : "=l"(d) : "l"(a), "l"(b));
    return d;
}
__device__ __forceinline__ ull pk(float lo, float hi) {
    ull r; asm("mov.b64 %0, {%1, %2};" : "=l"(r) : "f"(lo), "f"(hi));
    return r;
}
__device__ __forceinline__ void upk(ull v, float& lo, float& hi) {
    asm("mov.b64 {%0, %1}, %2;" : "=f"(lo), "=f"(hi) : "l"(v));
}
__device__ __forceinline__ ull swp(ull v) {
    float lo, hi; upk(v, lo, hi); return pk(hi, lo);
}
__device__ __forceinline__ float ldcs(const float* p) {
    float v; asm volatile("ld.global.cs.f32 %0, [%1];" : "=f"(v) : "l"(p));
    return v;
}

// row0 of U = Rz@Ry@Rx (SU(2)): u00 = (u0,u1), u01 = (u2,u3)
__device__ __forceinline__ void make_row(const float* __restrict__ vp, int layer, int q,
                                         float& u0, float& u1, float& u2, float& u3) {
    const float* p = vp + ((layer * 16) + q) * 6;
    float tx = p[0], ty = p[1], tz = p[2];
    float cx = cosf(0.5f * tx), sx = sinf(0.5f * tx);
    float cy = cosf(0.5f * ty), sy = sinf(0.5f * ty);
    float cz = cosf(0.5f * tz), sz = sinf(0.5f * tz);
    float m00r =  cy * cx, m00i =  sy * sx;
    float m01r = -sy * cx, m01i = -cy * sx;
    u0 = cz * m00r + sz * m00i; u1 = cz * m00i - sz * m00r;
    u2 = cz * m01r + sz * m01i; u3 = cz * m01i - sz * m01r;
}
__device__ __forceinline__ void make_g7(const float* vp, int layer, int q, G7* g) {
    float u0, u1, u2, u3; make_row(vp, layer, q, u0, u1, u2, u3);
    g->ar  = pk(u0, u0);  g->ai  = pk(u1, u1);  g->nai = pk(-u1, -u1);
    g->br  = pk(u2, u2);  g->bi  = pk(u3, u3);
    g->nbr = pk(-u2, -u2); g->nbi = pk(-u3, -u3);
}
__device__ __forceinline__ void make_gl(const float* vp, int layer, int q, GL* g) {
    float u0, u1, u2, u3; make_row(vp, layer, q, u0, u1, u2, u3);
    g->p1 = pk(u0, u0);   g->p2 = pk(u2, -u2);
    g->p3 = pk(-u1, u1);  g->p4 = pk(-u3, -u3);
    g->q1 = pk(u1, -u1);  g->q2 = pk(u3, u3);
    g->q3 = pk(u0, u0);   g->q4 = pk(u2, -u2);
}

// swap-free SoA SU(2) gate on slot pair (a,b)
__device__ __forceinline__ void vgate(ull& rea, ull& ima, ull& reb, ull& imb,
                                      const G7& g) {
    ull nra = f2fma(g.ar,  rea, f2fma(g.nai, ima, f2fma(g.br,  reb, f2mul(g.nbi, imb))));
    ull nia = f2fma(g.ai,  rea, f2fma(g.ar,  ima, f2fma(g.bi,  reb, f2mul(g.br,  imb))));
    ull nrb = f2fma(g.nbr, rea, f2fma(g.nbi, ima, f2fma(g.ar,  reb, f2mul(g.ai,  imb))));
    ull nib = f2fma(g.bi,  rea, f2fma(g.nbr, ima, f2fma(g.nai, reb, f2mul(g.ar,  imb))));
    rea = nra; ima = nia; reb = nrb; imb = nib;
}

__device__ __forceinline__ void level(ull* __restrict__ rev, ull* __restrict__ imv,
                                      const G7& gsm, int s) {
    G7 g = gsm;
#pragma unroll
    for (int r0 = 0; r0 < 8; r0++) {
        if (r0 & s) continue;
        vgate(rev[r0], imv[r0], rev[r0 | s], imv[r0 | s], g);
    }
}
__device__ __forceinline__ void level16(ull* __restrict__ rev, ull* __restrict__ imv,
                                        const G7& gsm, int s) {
    G7 g = gsm;
#pragma unroll
    for (int r0 = 0; r0 < 16; r0++) {
        if (r0 & s) continue;
        vgate(rev[r0], imv[r0], rev[r0 | s], imv[r0 | s], g);
    }
}

// in-lane gate across bit 15 (the packed lane)
__device__ __forceinline__ void inlane16(ull* __restrict__ rev, ull* __restrict__ imv,
                                         const GL& gsm) {
    GL g = gsm;
#pragma unroll
    for (int k = 0; k < 16; k++) {
        ull sR = swp(rev[k]), sI = swp(imv[k]);
        ull nR = f2fma(g.p1, rev[k], f2fma(g.p2, sR, f2fma(g.p3, imv[k], f2mul(g.p4, sI))));
        ull nI = f2fma(g.q1, rev[k], f2fma(g.q2, sR, f2fma(g.q3, imv[k], f2mul(g.q4, sI))));
        rev[k] = nR; imv[k] = nI;
    }
}

// ---------------------------------------------------------------------------
// Pass A (R12-verified): rotations qubits 5..15 (j bits [10:0]). Tile =
// j[10:0], tile id = j[14:11]; grid = batch(6b)<<4 | tile(4b). If !fromInput,
// load applies deferred chain q=1..14: a = j ^ ((j>>1)&0x3FFF).
// Layer 0 also seeds out[] = hb[0] and uses evict-first input loads.
// ---------------------------------------------------------------------------
__global__ void __launch_bounds__(THREADS, 4)
passA(const float* __restrict__ sr, const float* __restrict__ si,
      const ulonglong2* __restrict__ src, ulonglong2* __restrict__ dst,
      const float* __restrict__ vp, float* __restrict__ out,
      const float* __restrict__ hb, int layer, int fromInput) {
    __shared__ ulonglong2 amp[PAD_SLOTS];
    __shared__ G7 um[11];
    int tid = threadIdx.x;
    int batch = blockIdx.x >> 4, tileid = blockIdx.x & 15;
    int base  = batch << 15;
    int tbase = tileid << 11;

    if (tid < 11) make_g7(vp, layer, 15 - tid, &um[tid]);
    __syncthreads();

    ull rev[8], imv[8];

    if (fromInput) {
        if (tid == 0 && tileid == 0) out[batch] = hb[0];   // init output
        const float* srb = sr + (batch << 16);
        const float* sib = si + (batch << 16);
#pragma unroll
        for (int k = 0; k < 8; k++) {
            int j = tbase | (k << 8) | tid;
            rev[k] = pk(ldcs(&srb[j]), ldcs(&srb[j | 0x8000]));
            imv[k] = pk(ldcs(&sib[j]), ldcs(&sib[j | 0x8000]));
        }
    } else {
#pragma unroll
        for (int k = 0; k < 8; k++) {
            int j = tbase | (k << 8) | tid;
            int a = j ^ ((j >> 1) & 0x3FFF);       // chain q=1..14, lane-invariant
            ulonglong2 v = src[base + a];
            rev[k] = v.x; imv[k] = v.y;
        }
    }

    // m1: bits 8,9,10 (qubits 7,6,5)
    level(rev, imv, um[8], 1);
    level(rev, imv, um[9], 2);
    level(rev, imv, um[10], 4);

    // transpose m1 -> m2
#pragma unroll
    for (int k = 0; k < 8; k++) {
        int t = (k << 8) | tid;
        amp[t + (t >> 3)] = make_ulonglong2(rev[k], imv[k]);
    }
    __syncthreads();
#pragma unroll
    for (int k = 0; k < 8; k++) {
        int t = (tid << 3) | k;
        ulonglong2 v = amp[t + (t >> 3)];
        rev[k] = v.x; imv[k] = v.y;
    }

    // m2: bits 0,1,2 (qubits 15,14,13)
    level(rev, imv, um[0], 1);
    level(rev, imv, um[1], 2);
    level(rev, imv, um[2], 4);

    // transpose m2 -> m3
    __syncthreads();
#pragma unroll
    for (int k = 0; k < 8; k++) {
        int t = (tid << 3) | k;
        amp[t + (t >> 3)] = make_ulonglong2(rev[k], imv[k]);
    }
    __syncthreads();
#pragma unroll
    for (int k = 0; k < 8; k++) {
        int t = ((tid >> 3) << 6) | (k << 3) | (tid & 7);
        ulonglong2 v = amp[t + (t >> 3)];
        rev[k] = v.x; imv[k] = v.y;
    }

    // m3: bits 3,4,5 (qubits 12,11,10)
    level(rev, imv, um[3], 1);
    level(rev, imv, um[4], 2);
    level(rev, imv, um[5], 4);

    // transpose m3 -> m4
    __syncthreads();
#pragma unroll
    for (int k = 0; k < 8; k++) {
        int t = ((tid >> 3) << 6) | (k << 3) | (tid & 7);
        amp[t + (t >> 3)] = make_ulonglong2(rev[k], imv[k]);
    }
    __syncthreads();
#pragma unroll
    for (int k = 0; k < 8; k++) {
        int t = ((tid >> 5) << 8) | (k << 5) | (tid & 31);
        ulonglong2 v = amp[t + (t >> 3)];
        rev[k] = v.x; imv[k] = v.y;
    }

    // m4: bits 6,7 (qubits 9,8)
    level(rev, imv, um[6], 2);
    level(rev, imv, um[7], 4);

    // store from m4 (coalesced)
#pragma unroll
    for (int k = 0; k < 8; k++) {
        int t = ((tid >> 5) << 8) | (k << 5) | (tid & 31);
        dst[base + (tbase | t)] = make_ulonglong2(rev[k], imv[k]);
    }
}

// ---------------------------------------------------------------------------
// Pass B: register-only 16-slot kernel, IN-PLACE (buf==src==dst; each thread
// reads exactly the addresses it writes). grid = batch(6b)<<3 | m(3b) = 512.
// j = (k<<11) | (m<<8) | tid :
//   slot bit 0 = j11 = qubit 4 (s=1), bit1 = j12 = qubit 3 (s=2),
//   bit2 = j13 = qubit 2 (s=4), bit3 = j14 = qubit 1 (s=8);
//   packed lane = bit15 = qubit 0 (inlane16).
// CNOT(0,1): hi-lane exchange between slots k and k^8 (j14 flip).
// ---------------------------------------------------------------------------
__global__ void __launch_bounds__(THREADS, 2)
passB(ulonglong2* __restrict__ buf, const float* __restrict__ vp, int layer) {
    __shared__ G7 um[4];
    __shared__ GL gl;
    int tid = threadIdx.x;
    int batch = blockIdx.x >> 3, m = blockIdx.x & 7;
    int base = batch << 15;

    if (tid < 4) make_g7(vp, layer, 4 - tid, &um[tid]);   // um[0]=q4 .. um[3]=q1
    else if (tid == 4) make_gl(vp, layer, 0, &gl);
    __syncthreads();

    int jbase = (m << 8) | tid;

    ull rev[16], imv[16];
#pragma unroll
    for (int k = 0; k < 16; k++) {
        ulonglong2 v = buf[base + ((k << 11) | jbase)];
        rev[k] = v.x; imv[k] = v.y;
    }

    level16(rev, imv, um[0], 1);   // qubit 4 (j11)
    level16(rev, imv, um[1], 2);   // qubit 3 (j12)
    level16(rev, imv, um[2], 4);   // qubit 2 (j13)
    level16(rev, imv, um[3], 8);   // qubit 1 (j14)
    inlane16(rev, imv, gl);        // qubit 0 (lane)

    // CNOT(0,1): new lane1 of slot k = old lane1 of slot k^8 (j14 flip)
#pragma unroll
    for (int k = 0; k < 8; k++) {
        float lo0, hi0, lo1, hi1;
        upk(rev[k], lo0, hi0); upk(rev[k | 8], lo1, hi1);
        rev[k] = pk(lo0, hi1); rev[k | 8] = pk(lo1, hi0);
        upk(imv[k], lo0, hi0); upk(imv[k | 8], lo1, hi1);
        imv[k] = pk(lo0, hi1); imv[k | 8] = pk(lo1, hi0);
    }

#pragma unroll
    for (int k = 0; k < 16; k++)
        buf[base + ((k << 11) | jbase)] = make_ulonglong2(rev[k], imv[k]);
}

// ---------------------------------------------------------------------------
// Pass B measure: same gates (no CNOT exchange); fold ENTIRE final chain
// q=0..14 into the parity: f = suffix-XOR of j; lane1 flips all signs.
// ---------------------------------------------------------------------------
__global__ void __launch_bounds__(THREADS, 2)
passBmeas(const ulonglong2* __restrict__ src, const float* __restrict__ vp,
          const float* __restrict__ hw, float* __restrict__ out, int layer) {
    __shared__ G7 um[4];
    __shared__ GL gl;
    __shared__ float feats[16];
    int tid = threadIdx.x;
    int l = tid & 31;
    int batch = blockIdx.x >> 3, m = blockIdx.x & 7;
    int base = batch << 15;

    if (tid < 4) make_g7(vp, layer, 4 - tid, &um[tid]);
    else if (tid == 4) make_gl(vp, layer, 0, &gl);
    if (tid < 16) feats[tid] = 0.0f;
    __syncthreads();

    int jbase = (m << 8) | tid;

    ull rev[16], imv[16];
#pragma unroll
    for (int k = 0; k < 16; k++) {
        ulonglong2 v = src[base + ((k << 11) | jbase)];
        rev[k] = v.x; imv[k] = v.y;
    }

    level16(rev, imv, um[0], 1);
    level16(rev, imv, um[1], 2);
    level16(rev, imv, um[2], 4);
    level16(rev, imv, um[3], 8);
    inlane16(rev, imv, gl);

    float acc[16];
#pragma unroll
    for (int q = 0; q < 16; q++) acc[q] = 0.0f;
#pragma unroll
    for (int k = 0; k < 16; k++) {
        int j = (k << 11) | jbase;
        ull p = f2fma(rev[k], rev[k], f2mul(imv[k], imv[k]));
        float p0, p1; upk(p, p0, p1);
        float d = p0 - p1;                   // lane1 flips all signs
        int f = j;                           // suffix-XOR parity over j bits
        f ^= f >> 1; f ^= f >> 2; f ^= f >> 4; f ^= f >> 8;
#pragma unroll
        for (int q = 0; q < 16; q++)
            acc[q] += ((f >> (15 - q)) & 1) ? -d : d;
    }
#pragma unroll
    for (int q = 0; q < 16; q++) {
#pragma unroll
        for (int off = 16; off; off >>= 1)
            acc[q] += __shfl_xor_sync(0xffffffffu, acc[q], off);
    }
    if (l == 0) {
#pragma unroll
        for (int q = 0; q < 16; q++) atomicAdd(&feats[q], acc[q]);
    }
    __syncthreads();
    if (tid == 0) {
        float v = 0.0f;
        for (int q = 0; q < 16; q++) v += feats[q] * hw[q];
        atomicAdd(&out[batch], v);
    }
}

extern "C" void kernel_launch(void* const* d_in, const int* in_sizes, int n_in,
                              void* d_out, int out_size) {
    const float* sr = (const float*)d_in[0];
    const float* si = (const float*)d_in[1];
    const float* vp = (const float*)d_in[2];
    const float* hw = (const float*)d_in[3];
    const float* hb = (const float*)d_in[4];
    float* out = (float*)d_out;

    ulonglong2 *b0, *b1;
    cudaGetSymbolAddress((void**)&b0, g_bufA);
    cudaGetSymbolAddress((void**)&b1, g_bufB);

    // layer 0 (also seeds out[] = bias)
    passA<<<1024, THREADS>>>(sr, si, nullptr, b0, vp, out, hb, 0, 1);
    passB<<<512, THREADS>>>(b0, vp, 0);                       // in-place
    // layer 1 (perm reads b0, writes b1)
    passA<<<1024, THREADS>>>(nullptr, nullptr, b0, b1, vp, nullptr, nullptr, 1, 0);
    passB<<<512, THREADS>>>(b1, vp, 1);                       // in-place
    // layer 2 (perm reads b1, writes b0)
    passA<<<1024, THREADS>>>(nullptr, nullptr, b1, b0, vp, nullptr, nullptr, 2, 0);
    passBmeas<<<512, THREADS>>>(b0, vp, hw, out, 2);
}

// round 17
// speedup vs baseline: 1.0342x; 1.0342x over previous
#include <cuda_runtime.h>
#include <cstdint>

// ============================================================================
// 16-qubit statevector simulator, 64 batches, 3 layers (Rot x16 + CNOT chain).
// Round 17: R15 passA (best measured) + high-concurrency B-pass:
//  * passB/passBmeas: 128 threads, 8 slots, grid 2048, launch_bounds(128,8)
//    -> up to 32 warps/SM and 2048 CTAs of load concurrency (vs 512@occ2).
//    Math identical to R12-verified: slots=j[14:12] (q1..q3), q4 via
//    shfl_xor(16), q0 in-lane, CNOT(0,1) = hi-lane exchange k<->k^4.
//  * Ping-pong buffers (in-place reverted); input loads ld.global.cs.
//  * passA: bit-15 f32x2 packing, swap-free vgates, deferred CNOT chain
//    q=1..14 in load perm; full chain folded into measurement parity.
// ============================================================================

#define THREADS   256
#define BTHREADS  128
#define PAD_SLOTS (2048 + 256)    // slot = t + (t>>3), 16B elements

typedef unsigned long long ull;

__device__ ulonglong2 g_bufA[64 * 32768];
__device__ ulonglong2 g_bufB[64 * 32768];

struct G7 { ull ar, ai, nai, br, bi, nbr, nbi; };   // swap-free vgate coeffs
struct GL { ull p1, p2, p3, p4, q1, q2, q3, q4; };  // in-lane (bit15) coeffs

// ---------------- packed f32x2 primitives ----------------
__device__ __forceinline__ ull f2fma(ull a, ull b, ull c) {
    ull d; asm("fma.rn.f32x2 %0, %1, %2, %3;" : "=l"(d) : "l"(a), "l"(b), "l"(c));
    return d;
}
__device__ __forceinline__ ull f2mul(ull a, ull b) {
    ull d; asm("mul.rn.f32x2 %0, %1, %2;" : "=l"(d) : "l"(a), "l"(b));
    return d;
}
__device__ __forceinline__ ull pk(float lo, float hi) {
    ull r; asm("mov.b64 %0, {%1, %2};" : "=l"(r) : "f"(lo), "f"(hi));
    return r;
}
__device__ __forceinline__ void upk(ull v, float& lo, float& hi) {
    asm("mov.b64 {%0, %1}, %2;" : "=f"(lo), "=f"(hi) : "l"(v));
}
__device__ __forceinline__ ull swp(ull v) {
    float lo, hi; upk(v, lo, hi); return pk(hi, lo);
}
__device__ __forceinline__ float ldcs(const float* p) {
    float v; asm volatile("ld.global.cs.f32 %0, [%1];" : "=f"(v) : "l"(p));
    return v;
}

// row0 of U = Rz@Ry@Rx (SU(2)): u00 = (u0,u1), u01 = (u2,u3)
__device__ __forceinline__ void make_row(const float* __restrict__ vp, int layer, int q,
                                         float& u0, float& u1, float& u2, float& u3) {
    const float* p = vp + ((layer * 16) + q) * 6;
    float tx = p[0], ty = p[1], tz = p[2];
    float cx = cosf(0.5f * tx), sx = sinf(0.5f * tx);
    float cy = cosf(0.5f * ty), sy = sinf(0.5f * ty);
    float cz = cosf(0.5f * tz), sz = sinf(0.5f * tz);
    float m00r =  cy * cx, m00i =  sy * sx;
    float m01r = -sy * cx, m01i = -cy * sx;
    u0 = cz * m00r + sz * m00i; u1 = cz * m00i - sz * m00r;
    u2 = cz * m01r + sz * m01i; u3 = cz * m01i - sz * m01r;
}
__device__ __forceinline__ void make_g7(const float* vp, int layer, int q, G7* g) {
    float u0, u1, u2, u3; make_row(vp, layer, q, u0, u1, u2, u3);
    g->ar  = pk(u0, u0);  g->ai  = pk(u1, u1);  g->nai = pk(-u1, -u1);
    g->br  = pk(u2, u2);  g->bi  = pk(u3, u3);
    g->nbr = pk(-u2, -u2); g->nbi = pk(-u3, -u3);
}
__device__ __forceinline__ void make_gl(const float* vp, int layer, int q, GL* g) {
    float u0, u1, u2, u3; make_row(vp, layer, q, u0, u1, u2, u3);
    g->p1 = pk(u0, u0);   g->p2 = pk(u2, -u2);
    g->p3 = pk(-u1, u1);  g->p4 = pk(-u3, -u3);
    g->q1 = pk(u1, -u1);  g->q2 = pk(u3, u3);
    g->q3 = pk(u0, u0);   g->q4 = pk(u2, -u2);
}

// swap-free SoA SU(2) gate on slot pair (a,b)
__device__ __forceinline__ void vgate(ull& rea, ull& ima, ull& reb, ull& imb,
                                      const G7& g) {
    ull nra = f2fma(g.ar,  rea, f2fma(g.nai, ima, f2fma(g.br,  reb, f2mul(g.nbi, imb))));
    ull nia = f2fma(g.ai,  rea, f2fma(g.ar,  ima, f2fma(g.bi,  reb, f2mul(g.br,  imb))));
    ull nrb = f2fma(g.nbr, rea, f2fma(g.nbi, ima, f2fma(g.ar,  reb, f2mul(g.ai,  imb))));
    ull nib = f2fma(g.bi,  rea, f2fma(g.nbr, ima, f2fma(g.nai, reb, f2mul(g.ar,  imb))));
    rea = nra; ima = nia; reb = nrb; imb = nib;
}

__device__ __forceinline__ void level(ull* __restrict__ rev, ull* __restrict__ imv,
                                      const G7& gsm, int s) {
    G7 g = gsm;
#pragma unroll
    for (int r0 = 0; r0 < 8; r0++) {
        if (r0 & s) continue;
        vgate(rev[r0], imv[r0], rev[r0 | s], imv[r0 | s], g);
    }
}

// in-lane gate across bit 15 (the packed lane)
__device__ __forceinline__ void inlane8(ull* __restrict__ rev, ull* __restrict__ imv,
                                        const GL& gsm) {
    GL g = gsm;
#pragma unroll
    for (int k = 0; k < 8; k++) {
        ull sR = swp(rev[k]), sI = swp(imv[k]);
        ull nR = f2fma(g.p1, rev[k], f2fma(g.p2, sR, f2fma(g.p3, imv[k], f2mul(g.p4, sI))));
        ull nI = f2fma(g.q1, rev[k], f2fma(g.q2, sR, f2fma(g.q3, imv[k], f2mul(g.q4, sI))));
        rev[k] = nR; imv[k] = nI;
    }
}

// ---------------------------------------------------------------------------
// Pass A (R15, unchanged): rotations qubits 5..15 (j bits [10:0]). Tile =
// j[10:0], tile id = j[14:11]; grid = batch(6b)<<4 | tile(4b). If !fromInput,
// load applies deferred chain q=1..14: a = j ^ ((j>>1)&0x3FFF).
// Layer 0 also seeds out[] = hb[0] and uses evict-first input loads.
// ---------------------------------------------------------------------------
__global__ void __launch_bounds__(THREADS, 4)
passA(const float* __restrict__ sr, const float* __restrict__ si,
      const ulonglong2* __restrict__ src, ulonglong2* __restrict__ dst,
      const float* __restrict__ vp, float* __restrict__ out,
      const float* __restrict__ hb, int layer, int fromInput) {
    __shared__ ulonglong2 amp[PAD_SLOTS];
    __shared__ G7 um[11];
    int tid = threadIdx.x;
    int batch = blockIdx.x >> 4, tileid = blockIdx.x & 15;
    int base  = batch << 15;
    int tbase = tileid << 11;

    if (tid < 11) make_g7(vp, layer, 15 - tid, &um[tid]);
    __syncthreads();

    ull rev[8], imv[8];

    if (fromInput) {
        if (tid == 0 && tileid == 0) out[batch] = hb[0];   // init output
        const float* srb = sr + (batch << 16);
        const float* sib = si + (batch << 16);
#pragma unroll
        for (int k = 0; k < 8; k++) {
            int j = tbase | (k << 8) | tid;
            rev[k] = pk(ldcs(&srb[j]), ldcs(&srb[j | 0x8000]));
            imv[k] = pk(ldcs(&sib[j]), ldcs(&sib[j | 0x8000]));
        }
    } else {
#pragma unroll
        for (int k = 0; k < 8; k++) {
            int j = tbase | (k << 8) | tid;
            int a = j ^ ((j >> 1) & 0x3FFF);       // chain q=1..14, lane-invariant
            ulonglong2 v = src[base + a];
            rev[k] = v.x; imv[k] = v.y;
        }
    }

    // m1: bits 8,9,10 (qubits 7,6,5)
    level(rev, imv, um[8], 1);
    level(rev, imv, um[9], 2);
    level(rev, imv, um[10], 4);

    // transpose m1 -> m2
#pragma unroll
    for (int k = 0; k < 8; k++) {
        int t = (k << 8) | tid;
        amp[t + (t >> 3)] = make_ulonglong2(rev[k], imv[k]);
    }
    __syncthreads();
#pragma unroll
    for (int k = 0; k < 8; k++) {
        int t = (tid << 3) | k;
        ulonglong2 v = amp[t + (t >> 3)];
        rev[k] = v.x; imv[k] = v.y;
    }

    // m2: bits 0,1,2 (qubits 15,14,13)
    level(rev, imv, um[0], 1);
    level(rev, imv, um[1], 2);
    level(rev, imv, um[2], 4);

    // transpose m2 -> m3
    __syncthreads();
#pragma unroll
    for (int k = 0; k < 8; k++) {
        int t = (tid << 3) | k;
        amp[t + (t >> 3)] = make_ulonglong2(rev[k], imv[k]);
    }
    __syncthreads();
#pragma unroll
    for (int k = 0; k < 8; k++) {
        int t = ((tid >> 3) << 6) | (k << 3) | (tid & 7);
        ulonglong2 v = amp[t + (t >> 3)];
        rev[k] = v.x; imv[k] = v.y;
    }

    // m3: bits 3,4,5 (qubits 12,11,10)
    level(rev, imv, um[3], 1);
    level(rev, imv, um[4], 2);
    level(rev, imv, um[5], 4);

    // transpose m3 -> m4
    __syncthreads();
#pragma unroll
    for (int k = 0; k < 8; k++) {
        int t = ((tid >> 3) << 6) | (k << 3) | (tid & 7);
        amp[t + (t >> 3)] = make_ulonglong2(rev[k], imv[k]);
    }
    __syncthreads();
#pragma unroll
    for (int k = 0; k < 8; k++) {
        int t = ((tid >> 5) << 8) | (k << 5) | (tid & 31);
        ulonglong2 v = amp[t + (t >> 3)];
        rev[k] = v.x; imv[k] = v.y;
    }

    // m4: bits 6,7 (qubits 9,8)
    level(rev, imv, um[6], 2);
    level(rev, imv, um[7], 4);

    // store from m4 (coalesced)
#pragma unroll
    for (int k = 0; k < 8; k++) {
        int t = ((tid >> 5) << 8) | (k << 5) | (tid & 31);
        dst[base + (tbase | t)] = make_ulonglong2(rev[k], imv[k]);
    }
}

// ---------------------------------------------------------------------------
// Pass B: 128 threads, 8 slots, grid = batch(6b)<<5 | m(5b) = 2048 CTAs.
// j = (k<<12) | (t4<<11) | (m<<6) | jl, where t4 = tid[4],
// jl = (tid[6:5]<<4) | tid[3:0].
//   slots k = j[14:12] = qubits 1..3 (s=4,2,1); lane bit4 = j11 = qubit 4
//   (shfl_xor 16, R12-verified); packed lane = bit15 = qubit 0 (inlane8).
// CNOT(0,1): hi-lane exchange between slots k and k^4 (j14 flip).
// ---------------------------------------------------------------------------
__global__ void __launch_bounds__(BTHREADS, 8)
passB(const ulonglong2* __restrict__ src, ulonglong2* __restrict__ dst,
      const float* __restrict__ vp, int layer) {
    __shared__ G7 um[3];
    __shared__ GL gl;
    __shared__ float u4c[4];
    int tid = threadIdx.x;
    int batch = blockIdx.x >> 5, m = blockIdx.x & 31;
    int base = batch << 15;

    if (tid < 3) make_g7(vp, layer, 3 - tid, &um[tid]);   // um[0]=q3 um[1]=q2 um[2]=q1
    else if (tid == 3) make_gl(vp, layer, 0, &gl);
    else if (tid == 4) {
        float u0, u1, u2, u3; make_row(vp, layer, 4, u0, u1, u2, u3);
        u4c[0] = u0; u4c[1] = u1; u4c[2] = u2; u4c[3] = u3;
    }
    __syncthreads();

    int t4 = (tid >> 4) & 1;
    int jl = ((tid >> 5) << 4) | (tid & 15);
    int jbase = (t4 << 11) | (m << 6) | jl;

    ull rev[8], imv[8];
#pragma unroll
    for (int k = 0; k < 8; k++) {
        ulonglong2 v = src[base + ((k << 12) | jbase)];
        rev[k] = v.x; imv[k] = v.y;
    }

    level(rev, imv, um[0], 1);   // qubit 3 (j12)
    level(rev, imv, um[1], 2);   // qubit 2 (j13)
    level(rev, imv, um[2], 4);   // qubit 1 (j14)

    // qubit 4 (j11 = lane bit 4) via shfl  (R12-verified coefficients)
    {
        float u0 = u4c[0], u1 = u4c[1], u2 = u4c[2], u3 = u4c[3];
        float b = t4 ? u1 : -u1;
        float c = t4 ? -u2 : u2;
        ull U0 = pk(u0, u0), U3 = pk(u3, u3), nU3 = pk(-u3, -u3);
        ull Bv = pk(b, b), nBv = pk(-b, -b), Cv = pk(c, c);
#pragma unroll
        for (int k = 0; k < 8; k++) {
            ull pre = __shfl_xor_sync(0xffffffffu, rev[k], 16);
            ull pim = __shfl_xor_sync(0xffffffffu, imv[k], 16);
            ull nre = f2fma(U0, rev[k], f2fma(Bv, imv[k], f2fma(Cv, pre, f2mul(nU3, pim))));
            ull nim = f2fma(nBv, rev[k], f2fma(U0, imv[k], f2fma(U3, pre, f2mul(Cv, pim))));
            rev[k] = nre; imv[k] = nim;
        }
    }

    inlane8(rev, imv, gl);       // qubit 0 (lane)

    // CNOT(0,1): new lane1 of slot k = old lane1 of slot k^4 (j14 flip)
#pragma unroll
    for (int k = 0; k < 4; k++) {
        float lo0, hi0, lo1, hi1;
        upk(rev[k], lo0, hi0); upk(rev[k | 4], lo1, hi1);
        rev[k] = pk(lo0, hi1); rev[k | 4] = pk(lo1, hi0);
        upk(imv[k], lo0, hi0); upk(imv[k | 4], lo1, hi1);
        imv[k] = pk(lo0, hi1); imv[k | 4] = pk(lo1, hi0);
    }

#pragma unroll
    for (int k = 0; k < 8; k++)
        dst[base + ((k << 12) | jbase)] = make_ulonglong2(rev[k], imv[k]);
}

// ---------------------------------------------------------------------------
// Pass B measure: same gates (no CNOT exchange); fold ENTIRE final chain
// q=0..14 into the parity: f = suffix-XOR of j; lane1 flips all signs.
// ---------------------------------------------------------------------------
__global__ void __launch_bounds__(BTHREADS, 6)
passBmeas(const ulonglong2* __restrict__ src, const float* __restrict__ vp,
          const float* __restrict__ hw, float* __restrict__ out, int layer) {
    __shared__ G7 um[3];
    __shared__ GL gl;
    __shared__ float u4c[4];
    __shared__ float feats[16];
    int tid = threadIdx.x;
    int l = tid & 31;
    int batch = blockIdx.x >> 5, m = blockIdx.x & 31;
    int base = batch << 15;

    if (tid < 3) make_g7(vp, layer, 3 - tid, &um[tid]);
    else if (tid == 3) make_gl(vp, layer, 0, &gl);
    else if (tid == 4) {
        float u0, u1, u2, u3; make_row(vp, layer, 4, u0, u1, u2, u3);
        u4c[0] = u0; u4c[1] = u1; u4c[2] = u2; u4c[3] = u3;
    }
    if (tid < 16) feats[tid] = 0.0f;
    __syncthreads();

    int t4 = (tid >> 4) & 1;
    int jl = ((tid >> 5) << 4) | (tid & 15);
    int jbase = (t4 << 11) | (m << 6) | jl;

    ull rev[8], imv[8];
#pragma unroll
    for (int k = 0; k < 8; k++) {
        ulonglong2 v = src[base + ((k << 12) | jbase)];
        rev[k] = v.x; imv[k] = v.y;
    }

    level(rev, imv, um[0], 1);
    level(rev, imv, um[1], 2);
    level(rev, imv, um[2], 4);
    {
        float u0 = u4c[0], u1 = u4c[1], u2 = u4c[2], u3 = u4c[3];
        float b = t4 ? u1 : -u1;
        float c = t4 ? -u2 : u2;
        ull U0 = pk(u0, u0), U3 = pk(u3, u3), nU3 = pk(-u3, -u3);
        ull Bv = pk(b, b), nBv = pk(-b, -b), Cv = pk(c, c);
#pragma unroll
        for (int k = 0; k < 8; k++) {
            ull pre = __shfl_xor_sync(0xffffffffu, rev[k], 16);
            ull pim = __shfl_xor_sync(0xffffffffu, imv[k], 16);
            ull nre = f2fma(U0, rev[k], f2fma(Bv, imv[k], f2fma(Cv, pre, f2mul(nU3, pim))));
            ull nim = f2fma(nBv, rev[k], f2fma(U0, imv[k], f2fma(U3, pre, f2mul(Cv, pim))));
            rev[k] = nre; imv[k] = nim;
        }
    }
    inlane8(rev, imv, gl);

    // measurement with full-chain parity (lane1 flips all signs)
    float acc[16];
#pragma unroll
    for (int q = 0; q < 16; q++) acc[q] = 0.0f;
#pragma unroll
    for (int k = 0; k < 8; k++) {
        int j = (k << 12) | jbase;
        ull p = f2fma(rev[k], rev[k], f2mul(imv[k], imv[k]));
        float p0, p1; upk(p, p0, p1);
        float d = p0 - p1;
        int f = j;                           // suffix-XOR parity over j bits
        f ^= f >> 1; f ^= f >> 2; f ^= f >> 4; f ^= f >> 8;
#pragma unroll
        for (int q = 0; q < 16; q++)
            acc[q] += ((f >> (15 - q)) & 1) ? -d : d;
    }
#pragma unroll
    for (int q = 0; q < 16; q++) {
#pragma unroll
        for (int off = 16; off; off >>= 1)
            acc[q] += __shfl_xor_sync(0xffffffffu, acc[q], off);
    }
    if (l == 0) {
#pragma unroll
        for (int q = 0; q < 16; q++) atomicAdd(&feats[q], acc[q]);
    }
    __syncthreads();
    if (tid == 0) {
        float v = 0.0f;
        for (int q = 0; q < 16; q++) v += feats[q] * hw[q];
        atomicAdd(&out[batch], v);
    }
}

extern "C" void kernel_launch(void* const* d_in, const int* in_sizes, int n_in,
                              void* d_out, int out_size) {
    const float* sr = (const float*)d_in[0];
    const float* si = (const float*)d_in[1];
    const float* vp = (const float*)d_in[2];
    const float* hw = (const float*)d_in[3];
    const float* hb = (const float*)d_in[4];
    float* out = (float*)d_out;

    ulonglong2 *b0, *b1;
    cudaGetSymbolAddress((void**)&b0, g_bufA);
    cudaGetSymbolAddress((void**)&b1, g_bufB);

    // layer 0 (also seeds out[] = bias)
    passA<<<1024, THREADS>>>(sr, si, nullptr, b0, vp, out, hb, 0, 1);
    passB<<<2048, BTHREADS>>>(b0, b1, vp, 0);
    // layer 1 (perm reads b1, writes b0)
    passA<<<1024, THREADS>>>(nullptr, nullptr, b1, b0, vp, nullptr, nullptr, 1, 0);
    passB<<<2048, BTHREADS>>>(b0, b1, vp, 1);
    // layer 2
    passA<<<1024, THREADS>>>(nullptr, nullptr, b1, b0, vp, nullptr, nullptr, 2, 0);
    passBmeas<<<2048, BTHREADS>>>(b0, vp, hw, out, 2);
}